// round 1
// baseline (speedup 1.0000x reference)
#include <cuda_runtime.h>
#include <math.h>

#define N 4096
#define D 128
#define TM 128
#define TN 128
#define NTILES (N / TN)

// scratch (no allocations allowed)
__device__ float g_sq[2][N];     // squared norms of m1, m2 rows
__device__ int   g_t[N];         // targets as int32
__device__ float g_ap[4][N];     // masked row-max of squared dist, per combo
__device__ float g_an[4][N];     // masked row-min of squared dist, per combo

// ---------------------------------------------------------------------------
// prep: squared norms + target dtype detection/conversion
// ---------------------------------------------------------------------------
__global__ void prep_kernel(const float* __restrict__ m1,
                            const float* __restrict__ m2,
                            const unsigned int* __restrict__ tgt_raw) {
    int i = blockIdx.x * blockDim.x + threadIdx.x;
    if (i >= 2 * N) return;

    if (i < N) {
        // detect int64 vs int32: int64 little-endian with values in [0,512)
        // has zero high words. Check 32 odd words (cached, cheap).
        bool is64 = true;
        #pragma unroll
        for (int j = 0; j < 32; j++)
            if (tgt_raw[2 * j + 1] != 0u) is64 = false;
        g_t[i] = is64 ? (int)tgt_raw[2 * i] : (int)tgt_raw[i];
    }

    const float* src = (i < N) ? (m1 + (size_t)i * D)
                               : (m2 + (size_t)(i - N) * D);
    float s = 0.f;
    const float4* p = (const float4*)src;
    #pragma unroll
    for (int j = 0; j < D / 4; j++) {
        float4 v = p[j];
        s += v.x * v.x + v.y * v.y + v.z * v.z + v.w * v.w;
    }
    if (i < N) g_sq[0][i] = s;
    else       g_sq[1][i - N] = s;
}

// ---------------------------------------------------------------------------
// main: fused distance GEMM + masked row max/min
// combo 0: m1 x m1 | 1: m2 x m2 | 2: m1 x m2 | 3: m2 x m1
// ---------------------------------------------------------------------------
#define SMEM_FLOATS (D * TM + D * TN + TN)
#define SMEM_BYTES  (SMEM_FLOATS * 4 + TN * 4)

__global__ void __launch_bounds__(256, 1)
dist_kernel(const float* __restrict__ m1, const float* __restrict__ m2) {
    const int combo = blockIdx.y;
    const int rb    = blockIdx.x;

    const float* Q  = (combo & 1) ? m2 : m1;                    // 0,2 -> m1
    const float* Kp = (combo == 1 || combo == 2) ? m2 : m1;     // 0,3 -> m1
    const int qsi   = (combo & 1);
    const int ksi   = (combo == 1 || combo == 2) ? 1 : 0;

    extern __shared__ float smem[];
    float (*As)[TM] = (float (*)[TM])smem;                 // [D][TM] k-major
    float (*Bs)[TN] = (float (*)[TN])(smem + D * TM);      // [D][TN] k-major
    float* s_sqb    = smem + 2 * D * TM;                   // [TN]
    int*   s_tb     = (int*)(s_sqb + TN);                  // [TN]

    const int tid = threadIdx.x;
    const int tx  = tid & 15;
    const int ty  = tid >> 4;

    // load query tile transposed: As[k][r]
    {
        int r = tid >> 1, half = tid & 1;
        const float* src = Q + (size_t)(rb * TM + r) * D + half * 64;
        #pragma unroll
        for (int j = 0; j < 16; j++) {
            float4 v = ((const float4*)src)[j];
            int k = half * 64 + j * 4;
            As[k + 0][r] = v.x; As[k + 1][r] = v.y;
            As[k + 2][r] = v.z; As[k + 3][r] = v.w;
        }
    }

    // per-thread query metadata (8 rows)
    const int qbase = rb * TM + ty * 8;
    float sqa[8]; int ta[8];
    #pragma unroll
    for (int rr = 0; rr < 8; rr++) {
        sqa[rr] = g_sq[qsi][qbase + rr];
        ta[rr]  = g_t[qbase + rr];
    }

    float ap[8], an[8];
    #pragma unroll
    for (int rr = 0; rr < 8; rr++) { ap[rr] = -1e30f; an[rr] = 1e30f; }

    for (int kb = 0; kb < NTILES; kb++) {
        __syncthreads();
        // load key tile transposed: Bs[k][c]
        {
            int r = tid >> 1, half = tid & 1;
            const float* src = Kp + (size_t)(kb * TN + r) * D + half * 64;
            #pragma unroll
            for (int j = 0; j < 16; j++) {
                float4 v = ((const float4*)src)[j];
                int k = half * 64 + j * 4;
                Bs[k + 0][r] = v.x; Bs[k + 1][r] = v.y;
                Bs[k + 2][r] = v.z; Bs[k + 3][r] = v.w;
            }
            if (tid < TN) {
                s_sqb[tid] = g_sq[ksi][kb * TN + tid];
                s_tb[tid]  = g_t[kb * TN + tid];
            }
        }
        __syncthreads();

        float acc[8][8];
        #pragma unroll
        for (int a = 0; a < 8; a++)
            #pragma unroll
            for (int b = 0; b < 8; b++) acc[a][b] = 0.f;

        #pragma unroll 4
        for (int k = 0; k < D; k++) {
            float af[8], bf[8];
            *(float4*)&af[0] = *(const float4*)&As[k][ty * 8];
            *(float4*)&af[4] = *(const float4*)&As[k][ty * 8 + 4];
            *(float4*)&bf[0] = *(const float4*)&Bs[k][tx * 8];
            *(float4*)&bf[4] = *(const float4*)&Bs[k][tx * 8 + 4];
            #pragma unroll
            for (int a = 0; a < 8; a++)
                #pragma unroll
                for (int b = 0; b < 8; b++)
                    acc[a][b] = fmaf(af[a], bf[b], acc[a][b]);
        }

        // epilogue: squared distance + masked running max/min (sqrt deferred)
        #pragma unroll
        for (int b = 0; b < 8; b++) {
            float sqb = s_sqb[tx * 8 + b];
            int   tb  = s_tb[tx * 8 + b];
            #pragma unroll
            for (int a = 0; a < 8; a++) {
                float v = sqa[a] + sqb - 2.f * acc[a][b];
                if (ta[a] == tb) ap[a] = fmaxf(ap[a], v);
                else             an[a] = fminf(an[a], v);
            }
        }
    }

    // reduce across the 16 threads (tx) sharing each row.
    // lanes: tid%32 -> tx = lane&15; xor by 1,2,4,8 stays within the group.
    #pragma unroll
    for (int a = 0; a < 8; a++) {
        float p = ap[a], q = an[a];
        #pragma unroll
        for (int m = 1; m < 16; m <<= 1) {
            p = fmaxf(p, __shfl_xor_sync(0xffffffffu, p, m));
            q = fminf(q, __shfl_xor_sync(0xffffffffu, q, m));
        }
        if (tx == 0) {
            g_ap[combo][qbase + a] = p;
            g_an[combo][qbase + a] = q;
        }
    }
}

// ---------------------------------------------------------------------------
// finalize: sqrt + margin ranking loss + precision
// pairs: (ap1,an1)(ap2,an2)(ap3,an3)(ap4,an4)(ap3,an1)(ap4,an2)
// ---------------------------------------------------------------------------
__global__ void finalize_kernel(float* __restrict__ out, int out_size) {
    __shared__ float sl[256];
    __shared__ float sp[256];
    const int tid = threadIdx.x;
    float lsum = 0.f, psum = 0.f;

    const int pi[6] = {0, 1, 2, 3, 2, 3};
    const int ni[6] = {0, 1, 2, 3, 0, 1};

    for (int i = tid; i < N; i += 256) {
        float A[4], B[4];
        #pragma unroll
        for (int c = 0; c < 4; c++) {
            A[c] = sqrtf(fmaxf(g_ap[c][i], 1e-12f));
            B[c] = sqrtf(fmaxf(g_an[c][i], 1e-12f));
        }
        #pragma unroll
        for (int j = 0; j < 6; j++) {
            float apv = A[pi[j]], anv = B[ni[j]];
            lsum += fmaxf(apv - anv + 0.3f, 0.f);
            psum += (anv > apv) ? 1.f : 0.f;
        }
    }
    sl[tid] = lsum; sp[tid] = psum;
    __syncthreads();
    for (int s = 128; s > 0; s >>= 1) {
        if (tid < s) { sl[tid] += sl[tid + s]; sp[tid] += sp[tid + s]; }
        __syncthreads();
    }
    if (tid == 0) {
        const float inv = 1.f / (6.f * (float)N);
        if (out_size > 0) out[0] = sl[0] * inv;
        if (out_size > 1) out[1] = sp[0] * inv;
    }
}

// ---------------------------------------------------------------------------
extern "C" void kernel_launch(void* const* d_in, const int* in_sizes, int n_in,
                              void* d_out, int out_size) {
    const float* m1 = (const float*)d_in[0];
    const float* m2 = (const float*)d_in[1];
    const unsigned int* tgt = (const unsigned int*)d_in[2];
    float* out = (float*)d_out;

    cudaFuncSetAttribute(dist_kernel,
                         cudaFuncAttributeMaxDynamicSharedMemorySize,
                         SMEM_BYTES);

    prep_kernel<<<(2 * N + 255) / 256, 256>>>(m1, m2, tgt);
    dist_kernel<<<dim3(NTILES * TN / TM, 4), 256, SMEM_BYTES>>>(m1, m2);
    finalize_kernel<<<1, 256>>>(out, out_size);
}

// round 6
// speedup vs baseline: 2.5495x; 2.5495x over previous
#include <cuda_runtime.h>
#include <cuda_bf16.h>
#include <stdint.h>
#include <math.h>

#define N 4096
#define D 128
#define TM 128
#define TN 128
#define NT (N / TN)

// ---------------------------------------------------------------------------
// device scratch (no allocations allowed)
// ---------------------------------------------------------------------------
__device__ float g_sq[2][N];
__device__ int   g_t[N];
__device__ float g_ap[4][N];
__device__ float g_an[4][N];
// bf16 hi/lo splits, row-major [mat][row][col]
__device__ __align__(16) __nv_bfloat16 g_bfh[2][N][D];
__device__ __align__(16) __nv_bfloat16 g_bfl[2][N][D];

// ---------------------------------------------------------------------------
// helpers (all target-agnostic PTX: sm_80-era mma/ldmatrix/cp.async)
// ---------------------------------------------------------------------------
__device__ __forceinline__ uint32_t smem_u32(const void* p) {
    uint32_t a;
    asm("{ .reg .u64 t; cvta.to.shared.u64 t, %1; cvt.u32.u64 %0, t; }"
        : "=r"(a) : "l"(p));
    return a;
}
__device__ __forceinline__ void cpasync16(uint32_t d, const void* s) {
    asm volatile("cp.async.cg.shared.global [%0], [%1], 16;"
                 :: "r"(d), "l"(s) : "memory");
}
#define CP_COMMIT() asm volatile("cp.async.commit_group;" ::: "memory")
#define CP_WAIT0()  asm volatile("cp.async.wait_group 0;" ::: "memory")

__device__ __forceinline__ void ldsm4(uint32_t addr, uint32_t* r) {
    asm volatile("ldmatrix.sync.aligned.m8n8.x4.shared.b16 {%0,%1,%2,%3}, [%4];"
                 : "=r"(r[0]), "=r"(r[1]), "=r"(r[2]), "=r"(r[3]) : "r"(addr));
}
__device__ __forceinline__ void mma_bf16(float* c, const uint32_t* a,
                                         uint32_t b0, uint32_t b1) {
    asm volatile(
        "mma.sync.aligned.m16n8k16.row.col.f32.bf16.bf16.f32 "
        "{%0,%1,%2,%3}, {%4,%5,%6,%7}, {%8,%9}, {%0,%1,%2,%3};"
        : "+f"(c[0]), "+f"(c[1]), "+f"(c[2]), "+f"(c[3])
        : "r"(a[0]), "r"(a[1]), "r"(a[2]), "r"(a[3]), "r"(b0), "r"(b1));
}

// ---------------------------------------------------------------------------
// smem layout (bytes). Row stride 272B (136 bf16) kills ldmatrix conflicts.
// ---------------------------------------------------------------------------
#define RS        136
#define RB        272
#define A_BYTES   (128 * RB)            // 34816 per (hi|lo)
#define SMEM_AH   0
#define SMEM_AL   (SMEM_AH + A_BYTES)
#define SMEM_B    (SMEM_AL + A_BYTES)   // 2 bufs x (hi+lo)
#define BBUF      (2 * A_BYTES)
#define SMEM_MSQ  (SMEM_B + 2 * BBUF)   // float[2][128]
#define SMEM_MT   (SMEM_MSQ + 1024)     // int[2][128]
#define SMEM_RAP  (SMEM_MT + 1024)      // float[4][128]
#define SMEM_RAN  (SMEM_RAP + 2048)     // float[4][128]
#define SMEM_TOT  (SMEM_RAN + 2048)

// ---------------------------------------------------------------------------
// prep: squared norms + target dtype detection
// ---------------------------------------------------------------------------
__global__ void prep_kernel(const float* __restrict__ m1,
                            const float* __restrict__ m2,
                            const unsigned int* __restrict__ tgt_raw) {
    int i = blockIdx.x * blockDim.x + threadIdx.x;
    if (i >= 2 * N) return;
    if (i < N) {
        bool is64 = true;
        #pragma unroll
        for (int j = 0; j < 32; j++)
            if (tgt_raw[2 * j + 1] != 0u) is64 = false;
        g_t[i] = is64 ? (int)tgt_raw[2 * i] : (int)tgt_raw[i];
    }
    const float* src = (i < N) ? (m1 + (size_t)i * D) : (m2 + (size_t)(i - N) * D);
    float s = 0.f;
    const float4* p = (const float4*)src;
    #pragma unroll
    for (int j = 0; j < D / 4; j++) {
        float4 v = p[j];
        s += v.x * v.x + v.y * v.y + v.z * v.z + v.w * v.w;
    }
    if (i < N) g_sq[0][i] = s; else g_sq[1][i - N] = s;
}

// ---------------------------------------------------------------------------
// prep_bf: fp32 -> (hi, lo) bf16 row-major
// ---------------------------------------------------------------------------
__device__ __forceinline__ void split2(float x0, float x1, uint32_t& h, uint32_t& l) {
    __nv_bfloat162 hh = __floats2bfloat162_rn(x0, x1);
    float r0 = x0 - __bfloat162float(hh.x);
    float r1 = x1 - __bfloat162float(hh.y);
    __nv_bfloat162 ll = __floats2bfloat162_rn(r0, r1);
    h = *reinterpret_cast<uint32_t*>(&hh);
    l = *reinterpret_cast<uint32_t*>(&ll);
}
__global__ void prep_bf_kernel(const float* __restrict__ m1,
                               const float* __restrict__ m2) {
    int i = blockIdx.x * blockDim.x + threadIdx.x;  // 0..8191
    int mat = i >> 12, row = i & (N - 1);
    const float* src = (mat ? m2 : m1) + (size_t)row * D;
    uint2* dh = (uint2*)&g_bfh[mat][row][0];
    uint2* dl = (uint2*)&g_bfl[mat][row][0];
    const float4* s4 = (const float4*)src;
    #pragma unroll
    for (int j = 0; j < D / 4; j++) {
        float4 v = s4[j];
        uint32_t h0, h1, l0, l1;
        split2(v.x, v.y, h0, l0);
        split2(v.z, v.w, h1, l1);
        dh[j] = make_uint2(h0, h1);
        dl[j] = make_uint2(l0, l1);
    }
}

// ---------------------------------------------------------------------------
// tile copy: global row-major [128][128]bf16 -> smem padded rows (cp.async)
// ---------------------------------------------------------------------------
__device__ __forceinline__ void copy_tile(uint32_t dst, const __nv_bfloat16* src,
                                          int tid) {
    const uint4* s = (const uint4*)src;
    #pragma unroll
    for (int j = 0; j < 8; j++) {
        int i = tid + j * 256;          // 2048 16B chunks
        int row = i >> 4, c = i & 15;
        cpasync16(dst + row * RB + c * 16, s + i);
    }
}

// ---------------------------------------------------------------------------
// main fused kernel: bf16 3-term split on mma.sync + masked max/min epilogue
// ---------------------------------------------------------------------------
__global__ void __launch_bounds__(256, 1)
dist_mma_kernel() {
    extern __shared__ char smem[];
    const uint32_t sb = smem_u32(smem);
    const int tid = threadIdx.x, wid = tid >> 5, lid = tid & 31;
    const int combo = blockIdx.y, rb = blockIdx.x;
    const int qsi = combo & 1;
    const int ksi = (combo == 1 || combo == 2) ? 1 : 0;

    const int wm = wid & 1;             // M half (64 rows)
    const int wn = wid >> 1;            // N quarter (32 cols)
    const int g4 = lid >> 2, q4 = lid & 3;

    float* s_msq = (float*)(smem + SMEM_MSQ);
    int*   s_mt  = (int*)(smem + SMEM_MT);
    float* s_rap = (float*)(smem + SMEM_RAP);
    float* s_ran = (float*)(smem + SMEM_RAN);

    // prologue: A (hi+lo), B tile 0 (hi+lo), meta 0
    copy_tile(sb + SMEM_AH, &g_bfh[qsi][rb * TM][0], tid);
    copy_tile(sb + SMEM_AL, &g_bfl[qsi][rb * TM][0], tid);
    copy_tile(sb + SMEM_B,           &g_bfh[ksi][0][0], tid);
    copy_tile(sb + SMEM_B + A_BYTES, &g_bfl[ksi][0][0], tid);
    if (tid < 32)
        cpasync16(sb + SMEM_MSQ + tid * 16, (const char*)&g_sq[ksi][0] + tid * 16);
    else if (tid < 64)
        cpasync16(sb + SMEM_MT + (tid - 32) * 16,
                  (const char*)&g_t[0] + (tid - 32) * 16);
    CP_COMMIT();

    // per-thread row metadata: rows = rb*128 + wm*64 + mf*16 + g4 + half*8
    float sqa[4][2]; int ta[4][2];
    #pragma unroll
    for (int mf = 0; mf < 4; mf++)
        #pragma unroll
        for (int h = 0; h < 2; h++) {
            int r = rb * TM + wm * 64 + mf * 16 + g4 + h * 8;
            sqa[mf][h] = g_sq[qsi][r];
            ta[mf][h]  = g_t[r];
        }

    float ap[8], an[8];
    #pragma unroll
    for (int s = 0; s < 8; s++) { ap[s] = -1e30f; an[s] = 1e30f; }

    float acc[4][4][4];
    #pragma unroll
    for (int mf = 0; mf < 4; mf++)
        #pragma unroll
        for (int nf = 0; nf < 4; nf++)
            #pragma unroll
            for (int e = 0; e < 4; e++) acc[mf][nf][e] = 0.f;

    CP_WAIT0();
    __syncthreads();

    const int lg = lid >> 3, lr = lid & 7;     // ldmatrix lane decomposition

    for (int kb = 0; kb < NT; kb++) {
        const int cb = kb & 1;

        // prefetch next B tile + meta into other buffer
        if (kb < NT - 1) {
            const int nb = 1 - cb;
            copy_tile(sb + SMEM_B + nb * BBUF,
                      &g_bfh[ksi][(kb + 1) * TN][0], tid);
            copy_tile(sb + SMEM_B + nb * BBUF + A_BYTES,
                      &g_bfl[ksi][(kb + 1) * TN][0], tid);
            if (tid < 32)
                cpasync16(sb + SMEM_MSQ + nb * 512 + tid * 16,
                          (const char*)&g_sq[ksi][(kb + 1) * TN] + tid * 16);
            else if (tid < 64)
                cpasync16(sb + SMEM_MT + nb * 512 + (tid - 32) * 16,
                          (const char*)&g_t[(kb + 1) * TN] + (tid - 32) * 16);
        }
        CP_COMMIT();

        const uint32_t bH = sb + SMEM_B + cb * BBUF;
        const uint32_t bL = bH + A_BYTES;

        for (int ks = 0; ks < 8; ks++) {
            // A fragments (hi, lo): 4 m16 tiles
            uint32_t Ah[4][4], Al[4][4];
            #pragma unroll
            for (int mf = 0; mf < 4; mf++) {
                int mrow = wm * 64 + mf * 16 + (lg & 1) * 8 + lr;
                int kcol = ks * 16 + (lg >> 1) * 8;
                uint32_t off = (uint32_t)(mrow * RS + kcol) * 2;
                ldsm4(sb + SMEM_AH + off, Ah[mf]);
                ldsm4(sb + SMEM_AL + off, Al[mf]);
            }
            // B fragments (hi, lo): 2 n16 groups = 4 n8 tiles
            uint32_t Bh[2][4], Bl[2][4];
            #pragma unroll
            for (int ph = 0; ph < 2; ph++) {
                int nrow = wn * 32 + ph * 16 + (lg >> 1) * 8 + lr;
                int kcol = ks * 16 + (lg & 1) * 8;
                uint32_t off = (uint32_t)(nrow * RS + kcol) * 2;
                ldsm4(bH + off, Bh[ph]);
                ldsm4(bL + off, Bl[ph]);
            }
            // 3-term accumulate: hh + hl + lh
            #pragma unroll
            for (int mf = 0; mf < 4; mf++)
                #pragma unroll
                for (int nf = 0; nf < 4; nf++) {
                    const int ph = nf >> 1, sub = nf & 1;
                    mma_bf16(acc[mf][nf], Ah[mf], Bh[ph][2 * sub], Bh[ph][2 * sub + 1]);
                    mma_bf16(acc[mf][nf], Ah[mf], Bl[ph][2 * sub], Bl[ph][2 * sub + 1]);
                    mma_bf16(acc[mf][nf], Al[mf], Bh[ph][2 * sub], Bh[ph][2 * sub + 1]);
                }
        }

        // epilogue: squared distance + masked running max/min; reset accs
        #pragma unroll
        for (int nf = 0; nf < 4; nf++) {
            const int c0 = wn * 32 + nf * 8 + 2 * q4;
            const float sqb0 = s_msq[cb * 128 + c0];
            const float sqb1 = s_msq[cb * 128 + c0 + 1];
            const int   tb0  = s_mt[cb * 128 + c0];
            const int   tb1  = s_mt[cb * 128 + c0 + 1];
            #pragma unroll
            for (int mf = 0; mf < 4; mf++) {
                #pragma unroll
                for (int h = 0; h < 2; h++) {
                    const int s = mf * 2 + h;
                    float v0 = fmaf(acc[mf][nf][2 * h],     -2.f, sqa[mf][h] + sqb0);
                    float v1 = fmaf(acc[mf][nf][2 * h + 1], -2.f, sqa[mf][h] + sqb1);
                    if (ta[mf][h] == tb0) ap[s] = fmaxf(ap[s], v0);
                    else                  an[s] = fminf(an[s], v0);
                    if (ta[mf][h] == tb1) ap[s] = fmaxf(ap[s], v1);
                    else                  an[s] = fminf(an[s], v1);
                    acc[mf][nf][2 * h] = 0.f;
                    acc[mf][nf][2 * h + 1] = 0.f;
                }
            }
        }

        CP_WAIT0();
        __syncthreads();
    }

    // reduce across quad lanes (same rows, different cols)
    #pragma unroll
    for (int s = 0; s < 8; s++) {
        #pragma unroll
        for (int m = 1; m < 4; m <<= 1) {
            ap[s] = fmaxf(ap[s], __shfl_xor_sync(0xffffffffu, ap[s], m));
            an[s] = fminf(an[s], __shfl_xor_sync(0xffffffffu, an[s], m));
        }
    }
    if (q4 == 0) {
        #pragma unroll
        for (int mf = 0; mf < 4; mf++)
            #pragma unroll
            for (int h = 0; h < 2; h++) {
                int row = wm * 64 + mf * 16 + g4 + h * 8;
                s_rap[wn * 128 + row] = ap[mf * 2 + h];
                s_ran[wn * 128 + row] = an[mf * 2 + h];
            }
    }
    __syncthreads();
    if (tid < 128) {
        float p = s_rap[tid], q = s_ran[tid];
        #pragma unroll
        for (int w = 1; w < 4; w++) {
            p = fmaxf(p, s_rap[w * 128 + tid]);
            q = fminf(q, s_ran[w * 128 + tid]);
        }
        g_ap[combo][rb * TM + tid] = p;
        g_an[combo][rb * TM + tid] = q;
    }
}

// ---------------------------------------------------------------------------
// finalize: sqrt + margin ranking loss + precision
// ---------------------------------------------------------------------------
__global__ void finalize_kernel(float* __restrict__ out, int out_size) {
    __shared__ float sl[256];
    __shared__ float sp[256];
    const int tid = threadIdx.x;
    float lsum = 0.f, psum = 0.f;
    const int pi[6] = {0, 1, 2, 3, 2, 3};
    const int ni[6] = {0, 1, 2, 3, 0, 1};
    for (int i = tid; i < N; i += 256) {
        float A[4], B[4];
        #pragma unroll
        for (int c = 0; c < 4; c++) {
            A[c] = sqrtf(fmaxf(g_ap[c][i], 1e-12f));
            B[c] = sqrtf(fmaxf(g_an[c][i], 1e-12f));
        }
        #pragma unroll
        for (int j = 0; j < 6; j++) {
            float apv = A[pi[j]], anv = B[ni[j]];
            lsum += fmaxf(apv - anv + 0.3f, 0.f);
            psum += (anv > apv) ? 1.f : 0.f;
        }
    }
    sl[tid] = lsum; sp[tid] = psum;
    __syncthreads();
    for (int s = 128; s > 0; s >>= 1) {
        if (tid < s) { sl[tid] += sl[tid + s]; sp[tid] += sp[tid + s]; }
        __syncthreads();
    }
    if (tid == 0) {
        const float inv = 1.f / (6.f * (float)N);
        if (out_size > 0) out[0] = sl[0] * inv;
        if (out_size > 1) out[1] = sp[0] * inv;
    }
}

// ---------------------------------------------------------------------------
extern "C" void kernel_launch(void* const* d_in, const int* in_sizes, int n_in,
                              void* d_out, int out_size) {
    const float* m1 = (const float*)d_in[0];
    const float* m2 = (const float*)d_in[1];
    const unsigned int* tgt = (const unsigned int*)d_in[2];
    float* out = (float*)d_out;

    cudaFuncSetAttribute(dist_mma_kernel,
                         cudaFuncAttributeMaxDynamicSharedMemorySize, SMEM_TOT);

    prep_kernel<<<(2 * N + 255) / 256, 256>>>(m1, m2, tgt);
    prep_bf_kernel<<<(2 * N + 255) / 256, 256>>>(m1, m2);
    dist_mma_kernel<<<dim3(NT, 4), 256, SMEM_TOT>>>();
    finalize_kernel<<<1, 256>>>(out, out_size);
}

// round 7
// speedup vs baseline: 5.1946x; 2.0375x over previous
#include <cuda_runtime.h>
#include <cuda_bf16.h>
#include <stdint.h>
#include <math.h>

#define N 4096
#define D 128
#define TM 128
#define TN 128
#define NT (N / TN)
#define NCTA 288

// ---------------------------------------------------------------------------
// device scratch (no allocations allowed)
// ---------------------------------------------------------------------------
__device__ float    g_sq[2][N];
__device__ int      g_t[N];
__device__ unsigned g_apu[4][N];     // monotone-keyed squared-dist row max
__device__ unsigned g_anu[4][N];     // monotone-keyed squared-dist row min
__device__ float    g_part[16][2];
__device__ __align__(16) __nv_bfloat16 g_bfh[2][N][D];
__device__ __align__(16) __nv_bfloat16 g_bfl[2][N][D];

// ---------------------------------------------------------------------------
// helpers (target-agnostic PTX only: sm_80-era mma/ldmatrix/cp.async)
// ---------------------------------------------------------------------------
__device__ __forceinline__ uint32_t smem_u32(const void* p) {
    uint32_t a;
    asm("{ .reg .u64 t; cvta.to.shared.u64 t, %1; cvt.u32.u64 %0, t; }"
        : "=r"(a) : "l"(p));
    return a;
}
__device__ __forceinline__ void cpasync16(uint32_t d, const void* s) {
    asm volatile("cp.async.cg.shared.global [%0], [%1], 16;"
                 :: "r"(d), "l"(s) : "memory");
}
#define CP_COMMIT() asm volatile("cp.async.commit_group;" ::: "memory")
#define CP_WAIT0()  asm volatile("cp.async.wait_group 0;" ::: "memory")

__device__ __forceinline__ void ldsm4(uint32_t addr, uint32_t* r) {
    asm volatile("ldmatrix.sync.aligned.m8n8.x4.shared.b16 {%0,%1,%2,%3}, [%4];"
                 : "=r"(r[0]), "=r"(r[1]), "=r"(r[2]), "=r"(r[3]) : "r"(addr));
}
__device__ __forceinline__ void mma_bf16(float* c, const uint32_t* a,
                                         uint32_t b0, uint32_t b1) {
    asm volatile(
        "mma.sync.aligned.m16n8k16.row.col.f32.bf16.bf16.f32 "
        "{%0,%1,%2,%3}, {%4,%5,%6,%7}, {%8,%9}, {%0,%1,%2,%3};"
        : "+f"(c[0]), "+f"(c[1]), "+f"(c[2]), "+f"(c[3])
        : "r"(a[0]), "r"(a[1]), "r"(a[2]), "r"(a[3]), "r"(b0), "r"(b1));
}
// monotone float<->uint key (order-preserving, incl. negatives)
__device__ __forceinline__ unsigned fkey(float f) {
    unsigned b = __float_as_uint(f);
    return (b & 0x80000000u) ? ~b : (b | 0x80000000u);
}
__device__ __forceinline__ float funkey(unsigned k) {
    unsigned b = (k & 0x80000000u) ? (k & 0x7fffffffu) : ~k;
    return __uint_as_float(b);
}

// ---------------------------------------------------------------------------
// smem layout (bytes). Row stride 272B kills ldmatrix bank conflicts.
// ---------------------------------------------------------------------------
#define RS        136
#define RB        272
#define A_BYTES   (128 * RB)             // 34816 per (hi|lo)
#define SMEM_AH   0
#define SMEM_AL   (SMEM_AH + A_BYTES)
#define SMEM_B    (SMEM_AL + A_BYTES)    // 2 bufs x (hi+lo)
#define BBUF      (2 * A_BYTES)
#define SMEM_MSQ  (SMEM_B + 2 * BBUF)
#define SMEM_MT   (SMEM_MSQ + 1024)
#define SMEM_RAP  (SMEM_MT + 1024)
#define SMEM_RAN  (SMEM_RAP + 2048)
#define SMEM_TOT  (SMEM_RAN + 2048)

// ---------------------------------------------------------------------------
// prep: warp-per-row. norms (shfl-reduced), bf16 hi/lo split (coalesced),
// target conversion + keyed-reduction init.
// ---------------------------------------------------------------------------
__device__ __forceinline__ void split2(float x0, float x1, uint32_t& h, uint32_t& l) {
    __nv_bfloat162 hh = __floats2bfloat162_rn(x0, x1);
    float r0 = x0 - __bfloat162float(hh.x);
    float r1 = x1 - __bfloat162float(hh.y);
    __nv_bfloat162 ll = __floats2bfloat162_rn(r0, r1);
    h = *reinterpret_cast<uint32_t*>(&hh);
    l = *reinterpret_cast<uint32_t*>(&ll);
}

__global__ void prep2_kernel(const float* __restrict__ m1,
                             const float* __restrict__ m2,
                             const unsigned int* __restrict__ tgt_raw) {
    const int tid = threadIdx.x, lid = tid & 31, wid = tid >> 5;
    const int gw = blockIdx.x * 8 + wid;          // 0..8191 (warp = row)
    const int mat = gw >> 12, row = gw & (N - 1);
    const float* src = (mat ? m2 : m1) + (size_t)row * D;

    float4 v = ((const float4*)src)[lid];
    float s = v.x * v.x + v.y * v.y + v.z * v.z + v.w * v.w;
    #pragma unroll
    for (int m = 16; m; m >>= 1) s += __shfl_xor_sync(0xffffffffu, s, m);
    if (lid == 0) g_sq[mat][row] = s;

    uint32_t h0, h1, l0, l1;
    split2(v.x, v.y, h0, l0);
    split2(v.z, v.w, h1, l1);
    ((uint2*)&g_bfh[mat][row][0])[lid] = make_uint2(h0, h1);
    ((uint2*)&g_bfl[mat][row][0])[lid] = make_uint2(l0, l1);

    // targets + reduction init (first 16 blocks cover 4096)
    int t = blockIdx.x * 256 + tid;
    if (t < N) {
        bool is64 = true;
        #pragma unroll
        for (int j = 0; j < 32; j++)
            if (tgt_raw[2 * j + 1] != 0u) is64 = false;
        g_t[t] = is64 ? (int)tgt_raw[2 * t] : (int)tgt_raw[t];
        const unsigned kap = fkey(-1e30f), kan = fkey(1e30f);
        #pragma unroll
        for (int c = 0; c < 4; c++) {
            g_apu[c][t] = kap;
            g_anu[c][t] = kan;
        }
    }
}

// ---------------------------------------------------------------------------
// tile copy: global row-major [128][128]bf16 -> smem padded rows (cp.async)
// ---------------------------------------------------------------------------
__device__ __forceinline__ void copy_tile(uint32_t dst, const __nv_bfloat16* src,
                                          int tid) {
    const uint4* s = (const uint4*)src;
    #pragma unroll
    for (int j = 0; j < 8; j++) {
        int i = tid + j * 256;
        int row = i >> 4, c = i & 15;
        cpasync16(dst + row * RB + c * 16, s + i);
    }
}

// ---------------------------------------------------------------------------
// main fused kernel, work-list version.
// chunks: c<128 -> rt combo (full 32x32, col side feeds tr);
//         else  -> symmetric combos 0/1, upper-triangular tiles, col side
//                  feeds the same combo via transpose.
// ---------------------------------------------------------------------------
__global__ void __launch_bounds__(256, 1)
dist_mma_kernel() {
    extern __shared__ char smem[];
    const uint32_t sb = smem_u32(smem);
    const int tid = threadIdx.x, wid = tid >> 5, lid = tid & 31;

    // ---- work decode ----
    int combo, col_combo, rb, kb_lo, kb_hi;
    {
        int c = blockIdx.x;
        if (c < 128) {
            combo = 2; col_combo = 3;
            rb = c >> 2;
            kb_lo = (c & 3) * 8;
            kb_hi = kb_lo + 8;
        } else {
            int s = c - 128;
            combo = 0;
            if (s >= 80) { combo = 1; s -= 80; }
            col_combo = combo;
            int rbv = 0, jv = 0, s2 = s;
            #pragma unroll 1
            for (int r = 0; r < 32; r++) {
                int nch = 4 - (r >> 3);
                if (s2 < nch) { rbv = r; jv = (r >> 3) + s2; break; }
                s2 -= nch;
            }
            rb = rbv;
            kb_lo = max(rb, jv * 8);
            kb_hi = jv * 8 + 8;
        }
    }
    const int qsi = (combo == 1) ? 1 : 0;
    const int ksi = (combo == 0) ? 0 : 1;

    const int wm = wid & 1;             // M half (64 rows)
    const int wn = wid >> 1;            // N quarter (32 cols)
    const int g4 = lid >> 2, q4 = lid & 3;
    const int lg = lid >> 3, lr = lid & 7;

    float* s_msq = (float*)(smem + SMEM_MSQ);
    int*   s_mt  = (int*)(smem + SMEM_MT);
    float* s_rap = (float*)(smem + SMEM_RAP);
    float* s_ran = (float*)(smem + SMEM_RAN);

    // ---- prologue: A hi/lo + B(kb_lo) hi/lo + meta0 ----
    copy_tile(sb + SMEM_AH, &g_bfh[qsi][rb * TM][0], tid);
    copy_tile(sb + SMEM_AL, &g_bfl[qsi][rb * TM][0], tid);
    copy_tile(sb + SMEM_B,           &g_bfh[ksi][kb_lo * TN][0], tid);
    copy_tile(sb + SMEM_B + A_BYTES, &g_bfl[ksi][kb_lo * TN][0], tid);
    if (tid < 32)
        cpasync16(sb + SMEM_MSQ + tid * 16,
                  (const char*)&g_sq[ksi][kb_lo * TN] + tid * 16);
    else if (tid < 64)
        cpasync16(sb + SMEM_MT + (tid - 32) * 16,
                  (const char*)&g_t[kb_lo * TN] + (tid - 32) * 16);
    CP_COMMIT();

    // per-thread row metadata
    float sqa[4][2]; int ta[4][2];
    #pragma unroll
    for (int mf = 0; mf < 4; mf++)
        #pragma unroll
        for (int h = 0; h < 2; h++) {
            int r = rb * TM + wm * 64 + mf * 16 + g4 + h * 8;
            sqa[mf][h] = g_sq[qsi][r];
            ta[mf][h]  = g_t[r];
        }

    float ap[8], an[8];
    #pragma unroll
    for (int s = 0; s < 8; s++) { ap[s] = -1e30f; an[s] = 1e30f; }

    float acc[4][4][4];
    #pragma unroll
    for (int mf = 0; mf < 4; mf++)
        #pragma unroll
        for (int nf = 0; nf < 4; nf++)
            #pragma unroll
            for (int e = 0; e < 4; e++) acc[mf][nf][e] = 0.f;

    CP_WAIT0();
    __syncthreads();

    for (int kb = kb_lo; kb < kb_hi; kb++) {
        const int cb = (kb - kb_lo) & 1;

        if (kb + 1 < kb_hi) {
            const int nb = 1 - cb;
            copy_tile(sb + SMEM_B + nb * BBUF,
                      &g_bfh[ksi][(kb + 1) * TN][0], tid);
            copy_tile(sb + SMEM_B + nb * BBUF + A_BYTES,
                      &g_bfl[ksi][(kb + 1) * TN][0], tid);
            if (tid < 32)
                cpasync16(sb + SMEM_MSQ + nb * 512 + tid * 16,
                          (const char*)&g_sq[ksi][(kb + 1) * TN] + tid * 16);
            else if (tid < 64)
                cpasync16(sb + SMEM_MT + nb * 512 + (tid - 32) * 16,
                          (const char*)&g_t[(kb + 1) * TN] + (tid - 32) * 16);
        }
        CP_COMMIT();

        const uint32_t bH = sb + SMEM_B + cb * BBUF;
        const uint32_t bL = bH + A_BYTES;

        for (int ks = 0; ks < 8; ks++) {
            uint32_t Ah[4][4], Al[4][4];
            #pragma unroll
            for (int mf = 0; mf < 4; mf++) {
                int mrow = wm * 64 + mf * 16 + (lg & 1) * 8 + lr;
                int kcol = ks * 16 + (lg >> 1) * 8;
                uint32_t off = (uint32_t)(mrow * RS + kcol) * 2;
                ldsm4(sb + SMEM_AH + off, Ah[mf]);
                ldsm4(sb + SMEM_AL + off, Al[mf]);
            }
            uint32_t Bh[2][4], Bl[2][4];
            #pragma unroll
            for (int ph = 0; ph < 2; ph++) {
                int nrow = wn * 32 + ph * 16 + (lg >> 1) * 8 + lr;
                int kcol = ks * 16 + (lg & 1) * 8;
                uint32_t off = (uint32_t)(nrow * RS + kcol) * 2;
                ldsm4(bH + off, Bh[ph]);
                ldsm4(bL + off, Bl[ph]);
            }
            #pragma unroll
            for (int mf = 0; mf < 4; mf++)
                #pragma unroll
                for (int nf = 0; nf < 4; nf++) {
                    const int ph = nf >> 1, sub = nf & 1;
                    mma_bf16(acc[mf][nf], Ah[mf], Bh[ph][2 * sub], Bh[ph][2 * sub + 1]);
                    mma_bf16(acc[mf][nf], Ah[mf], Bl[ph][2 * sub], Bl[ph][2 * sub + 1]);
                    mma_bf16(acc[mf][nf], Al[mf], Bh[ph][2 * sub], Bh[ph][2 * sub + 1]);
                }
        }

        // ---- epilogue: row-side accumulate + col-side (transpose) ----
        const bool do_col = (combo == 2) || (kb != rb);
        float apc[4][2], anc[4][2];
        #pragma unroll
        for (int nf = 0; nf < 4; nf++)
            #pragma unroll
            for (int par = 0; par < 2; par++) {
                apc[nf][par] = -1e30f;
                anc[nf][par] = 1e30f;
            }

        #pragma unroll
        for (int nf = 0; nf < 4; nf++) {
            const int c0 = wn * 32 + nf * 8 + 2 * q4;
            const float sqb0 = s_msq[cb * 128 + c0];
            const float sqb1 = s_msq[cb * 128 + c0 + 1];
            const int   tb0  = s_mt[cb * 128 + c0];
            const int   tb1  = s_mt[cb * 128 + c0 + 1];
            #pragma unroll
            for (int mf = 0; mf < 4; mf++) {
                #pragma unroll
                for (int h = 0; h < 2; h++) {
                    const int s = mf * 2 + h;
                    float v0 = fmaf(acc[mf][nf][2 * h],     -2.f, sqa[mf][h] + sqb0);
                    float v1 = fmaf(acc[mf][nf][2 * h + 1], -2.f, sqa[mf][h] + sqb1);
                    if (ta[mf][h] == tb0) {
                        ap[s] = fmaxf(ap[s], v0);
                        apc[nf][0] = fmaxf(apc[nf][0], v0);
                    } else {
                        an[s] = fminf(an[s], v0);
                        anc[nf][0] = fminf(anc[nf][0], v0);
                    }
                    if (ta[mf][h] == tb1) {
                        ap[s] = fmaxf(ap[s], v1);
                        apc[nf][1] = fmaxf(apc[nf][1], v1);
                    } else {
                        an[s] = fminf(an[s], v1);
                        anc[nf][1] = fminf(anc[nf][1], v1);
                    }
                    acc[mf][nf][2 * h] = 0.f;
                    acc[mf][nf][2 * h + 1] = 0.f;
                }
            }
        }

        if (do_col) {
            #pragma unroll
            for (int nf = 0; nf < 4; nf++)
                #pragma unroll
                for (int par = 0; par < 2; par++) {
                    #pragma unroll
                    for (int m = 4; m < 32; m <<= 1) {
                        apc[nf][par] = fmaxf(apc[nf][par],
                            __shfl_xor_sync(0xffffffffu, apc[nf][par], m));
                        anc[nf][par] = fminf(anc[nf][par],
                            __shfl_xor_sync(0xffffffffu, anc[nf][par], m));
                    }
                }
            if (lid < 4) {
                #pragma unroll
                for (int nf = 0; nf < 4; nf++)
                    #pragma unroll
                    for (int par = 0; par < 2; par++) {
                        int j = kb * TN + wn * 32 + nf * 8 + 2 * lid + par;
                        atomicMax(&g_apu[col_combo][j], fkey(apc[nf][par]));
                        atomicMin(&g_anu[col_combo][j], fkey(anc[nf][par]));
                    }
            }
        }

        CP_WAIT0();
        __syncthreads();
    }

    // ---- row-side final reduce + atomics ----
    #pragma unroll
    for (int s = 0; s < 8; s++) {
        #pragma unroll
        for (int m = 1; m < 4; m <<= 1) {
            ap[s] = fmaxf(ap[s], __shfl_xor_sync(0xffffffffu, ap[s], m));
            an[s] = fminf(an[s], __shfl_xor_sync(0xffffffffu, an[s], m));
        }
    }
    if (q4 == 0) {
        #pragma unroll
        for (int mf = 0; mf < 4; mf++)
            #pragma unroll
            for (int h = 0; h < 2; h++) {
                int row = wm * 64 + mf * 16 + g4 + h * 8;
                s_rap[wn * 128 + row] = ap[mf * 2 + h];
                s_ran[wn * 128 + row] = an[mf * 2 + h];
            }
    }
    __syncthreads();
    if (tid < 128) {
        float p = s_rap[tid], q = s_ran[tid];
        #pragma unroll
        for (int w = 1; w < 4; w++) {
            p = fmaxf(p, s_rap[w * 128 + tid]);
            q = fminf(q, s_ran[w * 128 + tid]);
        }
        atomicMax(&g_apu[combo][rb * TM + tid], fkey(p));
        atomicMin(&g_anu[combo][rb * TM + tid], fkey(q));
    }
}

// ---------------------------------------------------------------------------
// finalize: stage 1 (16 blocks, 1 row/thread) + stage 2 (combine)
// pairs: (ap1,an1)(ap2,an2)(ap3,an3)(ap4,an4)(ap3,an1)(ap4,an2)
// ---------------------------------------------------------------------------
__global__ void finalize1_kernel() {
    __shared__ float sl[256];
    __shared__ float sp[256];
    const int tid = threadIdx.x;
    const int i = blockIdx.x * 256 + tid;
    const int pi[6] = {0, 1, 2, 3, 2, 3};
    const int ni[6] = {0, 1, 2, 3, 0, 1};
    float A[4], B[4];
    #pragma unroll
    for (int c = 0; c < 4; c++) {
        A[c] = sqrtf(fmaxf(funkey(g_apu[c][i]), 1e-12f));
        B[c] = sqrtf(fmaxf(funkey(g_anu[c][i]), 1e-12f));
    }
    float lsum = 0.f, psum = 0.f;
    #pragma unroll
    for (int j = 0; j < 6; j++) {
        float apv = A[pi[j]], anv = B[ni[j]];
        lsum += fmaxf(apv - anv + 0.3f, 0.f);
        psum += (anv > apv) ? 1.f : 0.f;
    }
    sl[tid] = lsum; sp[tid] = psum;
    __syncthreads();
    for (int s = 128; s > 0; s >>= 1) {
        if (tid < s) { sl[tid] += sl[tid + s]; sp[tid] += sp[tid + s]; }
        __syncthreads();
    }
    if (tid == 0) {
        g_part[blockIdx.x][0] = sl[0];
        g_part[blockIdx.x][1] = sp[0];
    }
}

__global__ void finalize2_kernel(float* __restrict__ out, int out_size) {
    const int tid = threadIdx.x;
    float l = 0.f, p = 0.f;
    if (tid < 16) { l = g_part[tid][0]; p = g_part[tid][1]; }
    #pragma unroll
    for (int m = 8; m; m >>= 1) {
        l += __shfl_xor_sync(0xffffffffu, l, m);
        p += __shfl_xor_sync(0xffffffffu, p, m);
    }
    if (tid == 0) {
        const float inv = 1.f / (6.f * (float)N);
        if (out_size > 0) out[0] = l * inv;
        if (out_size > 1) out[1] = p * inv;
    }
}

// ---------------------------------------------------------------------------
extern "C" void kernel_launch(void* const* d_in, const int* in_sizes, int n_in,
                              void* d_out, int out_size) {
    const float* m1 = (const float*)d_in[0];
    const float* m2 = (const float*)d_in[1];
    const unsigned int* tgt = (const unsigned int*)d_in[2];
    float* out = (float*)d_out;

    cudaFuncSetAttribute(dist_mma_kernel,
                         cudaFuncAttributeMaxDynamicSharedMemorySize, SMEM_TOT);

    prep2_kernel<<<1024, 256>>>(m1, m2, tgt);
    dist_mma_kernel<<<NCTA, 256, SMEM_TOT>>>();
    finalize1_kernel<<<16, 256>>>();
    finalize2_kernel<<<1, 32>>>(out, out_size);
}